// round 15
// baseline (speedup 1.0000x reference)
#include <cuda_runtime.h>
#include <math.h>

// ---------------- problem dims ----------------
#define BSZ 256
#define TT  128
#define FF  512
#define HH  1024
#define G4  4096

#define BKT 32   // k-elems per staged chunk
#define SAP 68   // sA row pitch (64 + 4): 272B rows -> 16B-aligned float4 reads

// ---------------- scratch (device globals) ----------------
__device__ float g_xproj[(size_t)BSZ * TT * G4]; // [B*T, 4H]
__device__ float g_gbuf[BSZ * G4];               // per-step gates
__device__ float g_pf[BSZ * HH];                 // c_{t-1} @ P_f (made by prev phaseB)
__device__ float g_pi[BSZ * HH];                 // c_{t-1} @ P_i
__device__ float g_h[BSZ * HH];
__device__ float g_c[BSZ * HH];

__device__ __forceinline__ float sigm(float v) { return 1.0f / (1.0f + expf(-v)); }

// ---------------- 64x64 GEMM core: reg-staged double buffer, 1 sync/chunk ---
// C(64x64) = A[m0.., :K] * B[:K, n0..]; A row-major [M,lda], B row-major [K,ldb].
// 256 threads; thread (tx,ty) owns rows ty*4..+3, cols tx*4..+3.
// sA: [buf][k][64+pad] (k-major), sB: [buf][k][64]. BK=32 -> 1 barrier per 32 k.
__device__ __forceinline__ void gemm_core(
    const float* __restrict__ A, int lda,
    const float* __restrict__ B, int ldb,
    int K, int m0, int n0,
    float* sA, float* sB, float acc[4][4])
{
    const int tid  = threadIdx.x;
    const int tx   = tid & 15;
    const int ty   = tid >> 4;
    // A loader: 2 float4/thread. e=tid -> (row, k4), e=tid+256 -> (row, k4+16)
    const int arow = tid & 63;          // 0..63
    const int ak4  = (tid >> 6) * 4;    // 0,4,8,12
    // B loader: 2 float4/thread. e=tid -> row tid>>4 (0..15), e=tid+256 -> +16
    const int brow = tid >> 4;          // 0..15
    const int bcol = (tid & 15) * 4;    // 0..60

    const int nkc = K / BKT;

    // preload chunk 0 -> regs -> buffer 0
    float4 ra0 = *(const float4*)&A[(size_t)(m0 + arow) * lda + ak4];
    float4 ra1 = *(const float4*)&A[(size_t)(m0 + arow) * lda + ak4 + 16];
    float4 rb0 = *(const float4*)&B[(size_t)brow * ldb + n0 + bcol];
    float4 rb1 = *(const float4*)&B[(size_t)(brow + 16) * ldb + n0 + bcol];
    {
        sA[(ak4 + 0) * 0 + (ak4 + 0) * SAP + arow] = ra0.x;   // (kept simple below)
        sA[(ak4 + 1) * SAP + arow] = ra0.y;
        sA[(ak4 + 2) * SAP + arow] = ra0.z;
        sA[(ak4 + 3) * SAP + arow] = ra0.w;
        sA[(ak4 + 0) * SAP + arow] = ra0.x;
        sA[(ak4 + 16) * SAP + arow] = ra1.x;
        sA[(ak4 + 17) * SAP + arow] = ra1.y;
        sA[(ak4 + 18) * SAP + arow] = ra1.z;
        sA[(ak4 + 19) * SAP + arow] = ra1.w;
        *(float4*)&sB[brow * 64 + bcol] = rb0;
        *(float4*)&sB[(brow + 16) * 64 + bcol] = rb1;
    }
    __syncthreads();

    for (int kc = 0; kc < nkc; kc++) {
        const float* bufA = sA + (kc & 1) * (BKT * SAP);
        const float* bufB = sB + (kc & 1) * (BKT * 64);
        const bool more = (kc + 1 < nkc);

        // issue next chunk's loads into registers (no dependent consumer yet)
        if (more) {
            const int kb = (kc + 1) * BKT;
            ra0 = *(const float4*)&A[(size_t)(m0 + arow) * lda + kb + ak4];
            ra1 = *(const float4*)&A[(size_t)(m0 + arow) * lda + kb + ak4 + 16];
            rb0 = *(const float4*)&B[(size_t)(kb + brow) * ldb + n0 + bcol];
            rb1 = *(const float4*)&B[(size_t)(kb + brow + 16) * ldb + n0 + bcol];
        }

        // compute on current buffer (overlaps in-flight LDGs)
#pragma unroll
        for (int k = 0; k < BKT; k++) {
            float4 aa = *(const float4*)&bufA[k * SAP + ty * 4];
            float4 bb = *(const float4*)&bufB[k * 64 + tx * 4];
            acc[0][0] += aa.x * bb.x; acc[0][1] += aa.x * bb.y; acc[0][2] += aa.x * bb.z; acc[0][3] += aa.x * bb.w;
            acc[1][0] += aa.y * bb.x; acc[1][1] += aa.y * bb.y; acc[1][2] += aa.y * bb.z; acc[1][3] += aa.y * bb.w;
            acc[2][0] += aa.z * bb.x; acc[2][1] += aa.z * bb.y; acc[2][2] += aa.z * bb.z; acc[2][3] += aa.z * bb.w;
            acc[3][0] += aa.w * bb.x; acc[3][1] += aa.w * bb.y; acc[3][2] += aa.w * bb.z; acc[3][3] += aa.w * bb.w;
        }

        // stage regs into the other buffer; one sync ends the chunk
        if (more) {
            float* nA = sA + ((kc & 1) ^ 1) * (BKT * SAP);
            float* nB = sB + ((kc & 1) ^ 1) * (BKT * 64);
            nA[(ak4 + 0) * SAP + arow] = ra0.x;
            nA[(ak4 + 1) * SAP + arow] = ra0.y;
            nA[(ak4 + 2) * SAP + arow] = ra0.z;
            nA[(ak4 + 3) * SAP + arow] = ra0.w;
            nA[(ak4 + 16) * SAP + arow] = ra1.x;
            nA[(ak4 + 17) * SAP + arow] = ra1.y;
            nA[(ak4 + 18) * SAP + arow] = ra1.z;
            nA[(ak4 + 19) * SAP + arow] = ra1.w;
            *(float4*)&nB[brow * 64 + bcol] = rb0;
            *(float4*)&nB[(brow + 16) * 64 + bcol] = rb1;
            __syncthreads();
        }
    }
}

#define GEMM_SMEM() \
    __shared__ float sA[2 * BKT * SAP]; \
    __shared__ float sB[2 * BKT * 64]; \
    float acc[4][4] = {}; \
    const int tx = threadIdx.x & 15; \
    const int ty = threadIdx.x >> 4;

// ---------------- kernels ---------------------------------------------------
__global__ void k_init()
{
    int idx = blockIdx.x * blockDim.x + threadIdx.x;
    if (idx < BSZ * HH) {
        g_h[idx] = 0.0f; g_c[idx] = 0.0f;
        g_pf[idx] = 0.0f; g_pi[idx] = 0.0f;   // c_{-1} @ P = 0
    }
}

// x_proj = x @ W_x + b    (M=32768, K=512, N=4096); grid (64, 512)
__global__ void k_xproj(const float* __restrict__ x,
                        const float* __restrict__ Wx,
                        const float* __restrict__ bias)
{
    const int m0 = blockIdx.y * 64, n0 = blockIdx.x * 64;
    GEMM_SMEM();
    gemm_core(x, FF, Wx, G4, FF, m0, n0, sA, sB, acc);

    const int cc = n0 + tx * 4;
    float4 bb = *(const float4*)&bias[cc];
#pragma unroll
    for (int i = 0; i < 4; i++) {
        size_t row = (size_t)m0 + ty * 4 + i;
        float4 v = make_float4(acc[i][0] + bb.x, acc[i][1] + bb.y,
                               acc[i][2] + bb.z, acc[i][3] + bb.w);
        *(float4*)&g_xproj[row * G4 + cc] = v;
    }
}

// phase A: gbuf = xp_t + h @ R_h   (N=4096); grid (64, 4)
__global__ void k_phaseA(const float* __restrict__ Rh, int t)
{
    const int m0 = blockIdx.y * 64, n0 = blockIdx.x * 64;
    GEMM_SMEM();
    gemm_core(g_h, HH, Rh, G4, HH, m0, n0, sA, sB, acc);

    const int cc = n0 + tx * 4;
#pragma unroll
    for (int i = 0; i < 4; i++) {
        size_t row = (size_t)m0 + ty * 4 + i;
        float4 xp = *(const float4*)&g_xproj[(row * TT + t) * (size_t)G4 + cc];
        float4 v = make_float4(acc[i][0] + xp.x, acc[i][1] + xp.y,
                               acc[i][2] + xp.z, acc[i][3] + xp.w);
        *(float4*)&g_gbuf[row * G4 + cc] = v;
    }
}

// cell update: uses pf/pi = c_{t-1} @ P_f/P_i (written by previous phaseB)
__global__ void k_cell()
{
    int idx = blockIdx.x * blockDim.x + threadIdx.x;
    if (idx >= BSZ * HH) return;
    int b = idx >> 10, j = idx & 1023;
    const float* gr = g_gbuf + (size_t)b * G4;
    float f = sigm(gr[j] + g_pf[idx]);
    float i = sigm(gr[HH + j] + g_pi[idx]);
    float ct = tanhf(gr[2 * HH + j]);
    g_c[idx] = g_c[idx] * f + ct * i;
}

// phase B (3 jobs, all A = c_t):  z0: h = tanh(c)*sigm(go + c@P_o)
//                                 z1: g_pf = c@P_f (for step t+1)
//                                 z2: g_pi = c@P_i (for step t+1)
// grid (16, 4, 3)
__global__ void k_phaseB(const float* __restrict__ Po,
                         const float* __restrict__ Pf,
                         const float* __restrict__ Pi,
                         float* __restrict__ dout, int last)
{
    const int z = blockIdx.z;
    const int m0 = blockIdx.y * 64, n0 = blockIdx.x * 64;
    GEMM_SMEM();

    if (z == 0)      gemm_core(g_c, HH, Po, HH, HH, m0, n0, sA, sB, acc);
    else if (z == 1) gemm_core(g_c, HH, Pf, HH, HH, m0, n0, sA, sB, acc);
    else             gemm_core(g_c, HH, Pi, HH, HH, m0, n0, sA, sB, acc);

    const int cc = n0 + tx * 4;
    if (z == 0) {
#pragma unroll
        for (int i = 0; i < 4; i++) {
            size_t row = (size_t)m0 + ty * 4 + i;
            float4 cv = *(const float4*)&g_c[row * HH + cc];
            float4 ov = *(const float4*)&g_gbuf[row * G4 + 3 * HH + cc];
            float4 v;
            v.x = tanhf(cv.x) * sigm(ov.x + acc[i][0]);
            v.y = tanhf(cv.y) * sigm(ov.y + acc[i][1]);
            v.z = tanhf(cv.z) * sigm(ov.z + acc[i][2]);
            v.w = tanhf(cv.w) * sigm(ov.w + acc[i][3]);
            *(float4*)&g_h[row * HH + cc] = v;
            if (last) *(float4*)&dout[row * HH + cc] = v;
        }
    } else {
        float* outp = (z == 1) ? g_pf : g_pi;
#pragma unroll
        for (int i = 0; i < 4; i++) {
            size_t row = (size_t)m0 + ty * 4 + i;
            float4 v = make_float4(acc[i][0], acc[i][1], acc[i][2], acc[i][3]);
            *(float4*)&outp[row * HH + cc] = v;
        }
    }
}

// ---------------- launch -----------------------------------------------------
extern "C" void kernel_launch(void* const* d_in, const int* in_sizes, int n_in,
                              void* d_out, int out_size)
{
    const float* x  = (const float*)d_in[0];
    const float* Wx = (const float*)d_in[1];
    const float* b  = (const float*)d_in[2];
    const float* Rh = (const float*)d_in[3];
    const float* Pf = (const float*)d_in[4];
    const float* Pi = (const float*)d_in[5];
    const float* Po = (const float*)d_in[6];
    float* out = (float*)d_out;
    (void)in_sizes; (void)n_in; (void)out_size;

    const int nElem = BSZ * HH;
    k_init<<<(nElem + 511) / 512, 512>>>();

    k_xproj<<<dim3(G4 / 64, (BSZ * TT) / 64), 256>>>(x, Wx, b);

    for (int t = 0; t < TT; t++) {
        k_phaseA<<<dim3(G4 / 64, BSZ / 64), 256>>>(Rh, t);
        k_cell<<<(nElem + 511) / 512, 512>>>();
        k_phaseB<<<dim3(HH / 64, BSZ / 64, 3), 256>>>(Po, Pf, Pi, out, (t == TT - 1) ? 1 : 0);
    }
}

// round 17
// speedup vs baseline: 1.1862x; 1.1862x over previous
#include <cuda_runtime.h>
#include <math.h>

// ---------------- problem dims ----------------
#define BSZ 256
#define TT  128
#define FF  512
#define HH  1024
#define G4  4096

#define SAP 68   // sA row pitch (64 + 4): 272B rows -> 16B-aligned float4 reads

// ---------------- scratch (device globals) ----------------
// xproj stored TRANSPOSED: [T][B][4H]  -> per-step reads are one contiguous 4MB block
__device__ float g_xproj[(size_t)TT * BSZ * G4];
__device__ float g_gbuf[BSZ * G4];               // per-step gates
__device__ float g_pf[BSZ * HH];                 // c_{t-1} @ P_f (made by prev phaseB)
__device__ float g_pi[BSZ * HH];                 // c_{t-1} @ P_i
__device__ float g_h[BSZ * HH];
__device__ float g_c[BSZ * HH];

__device__ __forceinline__ float sigm(float v) { return 1.0f / (1.0f + expf(-v)); }

// ---------------- 64x64 GEMM core: reg-staged double buffer, 1 sync/chunk ---
// C(64x64) = A[m0.., :K] * B[:K, n0..]; A row-major [M,lda], B row-major [K,ldb].
// 256 threads; thread (tx,ty) owns rows ty*4..+3, cols tx*4..+3.
// sA: [buf][k][64+pad] (k-major), sB: [buf][k][64].
__device__ __forceinline__ void gemm_core(
    const float* __restrict__ A, int lda,
    const float* __restrict__ B, int ldb,
    int K, int m0, int n0,
    float* sA, float* sB, float acc[4][4])
{
    const int tid  = threadIdx.x;
    const int tx   = tid & 15;
    const int ty   = tid >> 4;
    const int arow = tid >> 2;         // 0..63
    const int acol = (tid & 3) * 4;    // k offset 0,4,8,12
    const int brow = tid >> 4;         // 0..15
    const int bcol = (tid & 15) * 4;   // 0..60

    const int nkc = K / 16;

    // preload chunk 0 -> regs -> buffer 0
    float4 ra = *(const float4*)&A[(size_t)(m0 + arow) * lda + acol];
    float4 rb = *(const float4*)&B[(size_t)brow * ldb + n0 + bcol];
    sA[(acol + 0) * SAP + arow] = ra.x;
    sA[(acol + 1) * SAP + arow] = ra.y;
    sA[(acol + 2) * SAP + arow] = ra.z;
    sA[(acol + 3) * SAP + arow] = ra.w;
    *(float4*)&sB[brow * 64 + bcol] = rb;
    __syncthreads();

    for (int kc = 0; kc < nkc; kc++) {
        const float* bufA = sA + (kc & 1) * (16 * SAP);
        const float* bufB = sB + (kc & 1) * (16 * 64);
        const bool more = (kc + 1 < nkc);

        // issue next chunk's loads into registers (no dependent consumer yet)
        if (more) {
            const int kb = (kc + 1) * 16;
            ra = *(const float4*)&A[(size_t)(m0 + arow) * lda + kb + acol];
            rb = *(const float4*)&B[(size_t)(kb + brow) * ldb + n0 + bcol];
        }

        // compute on current buffer (overlaps in-flight LDGs)
#pragma unroll
        for (int k = 0; k < 16; k++) {
            float4 aa = *(const float4*)&bufA[k * SAP + ty * 4];
            float4 bb = *(const float4*)&bufB[k * 64 + tx * 4];
            acc[0][0] += aa.x * bb.x; acc[0][1] += aa.x * bb.y; acc[0][2] += aa.x * bb.z; acc[0][3] += aa.x * bb.w;
            acc[1][0] += aa.y * bb.x; acc[1][1] += aa.y * bb.y; acc[1][2] += aa.y * bb.z; acc[1][3] += aa.y * bb.w;
            acc[2][0] += aa.z * bb.x; acc[2][1] += aa.z * bb.y; acc[2][2] += aa.z * bb.z; acc[2][3] += aa.z * bb.w;
            acc[3][0] += aa.w * bb.x; acc[3][1] += aa.w * bb.y; acc[3][2] += aa.w * bb.z; acc[3][3] += aa.w * bb.w;
        }

        // stage regs into the other buffer; one sync ends the chunk
        if (more) {
            float* nA = sA + ((kc & 1) ^ 1) * (16 * SAP);
            float* nB = sB + ((kc & 1) ^ 1) * (16 * 64);
            nA[(acol + 0) * SAP + arow] = ra.x;
            nA[(acol + 1) * SAP + arow] = ra.y;
            nA[(acol + 2) * SAP + arow] = ra.z;
            nA[(acol + 3) * SAP + arow] = ra.w;
            *(float4*)&nB[brow * 64 + bcol] = rb;
            __syncthreads();
        }
    }
}

#define GEMM_SMEM() \
    __shared__ float sA[2 * 16 * SAP]; \
    __shared__ float sB[2 * 16 * 64]; \
    float acc[4][4] = {}; \
    const int tx = threadIdx.x & 15; \
    const int ty = threadIdx.x >> 4;

// ---------------- kernels ---------------------------------------------------
__global__ void k_init()
{
    int idx = blockIdx.x * blockDim.x + threadIdx.x;
    if (idx < BSZ * HH) {
        g_h[idx] = 0.0f; g_c[idx] = 0.0f;
        g_pf[idx] = 0.0f; g_pi[idx] = 0.0f;   // c_{-1} @ P = 0
    }
}

// x_proj = x @ W_x + b    (M=32768, K=512, N=4096); grid (64, 512)
// output scattered into transposed layout [t][b][4H]
__global__ void k_xproj(const float* __restrict__ x,
                        const float* __restrict__ Wx,
                        const float* __restrict__ bias)
{
    const int m0 = blockIdx.y * 64, n0 = blockIdx.x * 64;
    GEMM_SMEM();
    gemm_core(x, FF, Wx, G4, FF, m0, n0, sA, sB, acc);

    const int cc = n0 + tx * 4;
    float4 bb = *(const float4*)&bias[cc];
#pragma unroll
    for (int i = 0; i < 4; i++) {
        int row = m0 + ty * 4 + i;            // global m row = b*TT + t
        int b = row >> 7;                     // /TT
        int t = row & (TT - 1);
        size_t orow = (size_t)t * BSZ + b;    // [t][b]
        float4 v = make_float4(acc[i][0] + bb.x, acc[i][1] + bb.y,
                               acc[i][2] + bb.z, acc[i][3] + bb.w);
        *(float4*)&g_xproj[orow * G4 + cc] = v;
    }
}

// phase A: gbuf = xp_t + h @ R_h   (N=4096); grid (64, 4)
__global__ void k_phaseA(const float* __restrict__ Rh, int t)
{
    const int m0 = blockIdx.y * 64, n0 = blockIdx.x * 64;
    GEMM_SMEM();
    gemm_core(g_h, HH, Rh, G4, HH, m0, n0, sA, sB, acc);

    const int cc = n0 + tx * 4;
    const float* xpt = g_xproj + (size_t)t * BSZ * G4;   // contiguous 4MB slab
#pragma unroll
    for (int i = 0; i < 4; i++) {
        size_t row = (size_t)m0 + ty * 4 + i;
        float4 xp = *(const float4*)&xpt[row * G4 + cc];
        float4 v = make_float4(acc[i][0] + xp.x, acc[i][1] + xp.y,
                               acc[i][2] + xp.z, acc[i][3] + xp.w);
        *(float4*)&g_gbuf[row * G4 + cc] = v;
    }
}

// cell update: uses pf/pi = c_{t-1} @ P_f/P_i (written by previous phaseB)
__global__ void k_cell()
{
    int idx = blockIdx.x * blockDim.x + threadIdx.x;
    if (idx >= BSZ * HH) return;
    int b = idx >> 10, j = idx & 1023;
    const float* gr = g_gbuf + (size_t)b * G4;
    float f = sigm(gr[j] + g_pf[idx]);
    float i = sigm(gr[HH + j] + g_pi[idx]);
    float ct = tanhf(gr[2 * HH + j]);
    g_c[idx] = g_c[idx] * f + ct * i;
}

// phase B (3 jobs, all A = c_t):  z0: h = tanh(c)*sigm(go + c@P_o)
//                                 z1: g_pf = c@P_f (for step t+1)
//                                 z2: g_pi = c@P_i (for step t+1)
// grid (16, 4, 3)
__global__ void k_phaseB(const float* __restrict__ Po,
                         const float* __restrict__ Pf,
                         const float* __restrict__ Pi,
                         float* __restrict__ dout, int last)
{
    const int z = blockIdx.z;
    const int m0 = blockIdx.y * 64, n0 = blockIdx.x * 64;
    GEMM_SMEM();

    if (z == 0)      gemm_core(g_c, HH, Po, HH, HH, m0, n0, sA, sB, acc);
    else if (z == 1) gemm_core(g_c, HH, Pf, HH, HH, m0, n0, sA, sB, acc);
    else             gemm_core(g_c, HH, Pi, HH, HH, m0, n0, sA, sB, acc);

    const int cc = n0 + tx * 4;
    if (z == 0) {
#pragma unroll
        for (int i = 0; i < 4; i++) {
            size_t row = (size_t)m0 + ty * 4 + i;
            float4 cv = *(const float4*)&g_c[row * HH + cc];
            float4 ov = *(const float4*)&g_gbuf[row * G4 + 3 * HH + cc];
            float4 v;
            v.x = tanhf(cv.x) * sigm(ov.x + acc[i][0]);
            v.y = tanhf(cv.y) * sigm(ov.y + acc[i][1]);
            v.z = tanhf(cv.z) * sigm(ov.z + acc[i][2]);
            v.w = tanhf(cv.w) * sigm(ov.w + acc[i][3]);
            *(float4*)&g_h[row * HH + cc] = v;
            if (last) *(float4*)&dout[row * HH + cc] = v;
        }
    } else {
        float* outp = (z == 1) ? g_pf : g_pi;
#pragma unroll
        for (int i = 0; i < 4; i++) {
            size_t row = (size_t)m0 + ty * 4 + i;
            float4 v = make_float4(acc[i][0], acc[i][1], acc[i][2], acc[i][3]);
            *(float4*)&outp[row * HH + cc] = v;
        }
    }
}

// ---------------- launch -----------------------------------------------------
extern "C" void kernel_launch(void* const* d_in, const int* in_sizes, int n_in,
                              void* d_out, int out_size)
{
    const float* x  = (const float*)d_in[0];
    const float* Wx = (const float*)d_in[1];
    const float* b  = (const float*)d_in[2];
    const float* Rh = (const float*)d_in[3];
    const float* Pf = (const float*)d_in[4];
    const float* Pi = (const float*)d_in[5];
    const float* Po = (const float*)d_in[6];
    float* out = (float*)d_out;
    (void)in_sizes; (void)n_in; (void)out_size;

    const int nElem = BSZ * HH;
    k_init<<<(nElem + 511) / 512, 512>>>();

    k_xproj<<<dim3(G4 / 64, (BSZ * TT) / 64), 256>>>(x, Wx, b);

    for (int t = 0; t < TT; t++) {
        k_phaseA<<<dim3(G4 / 64, BSZ / 64), 256>>>(Rh, t);
        k_cell<<<(nElem + 511) / 512, 512>>>();
        k_phaseB<<<dim3(HH / 64, BSZ / 64, 3), 256>>>(Po, Pf, Pi, out, (t == TT - 1) ? 1 : 0);
    }
}